// round 3
// baseline (speedup 1.0000x reference)
#include <cuda_runtime.h>

// out[i] = sum_j S[i][j] * w[j],  N = 16384.
// Persistent one-wave kernel: grid = 148 SMs * 8 CTAs = 1184 blocks, each
// block grid-strides over rows. Eliminates ~13 wave transitions of the
// 16384-block launch (each ~2360 cyc of memory-pipe drain) that matched the
// 8.5% DRAM idle fraction in the R1 ncu profile.
// Weights read via __ldg each row: L1-resident after the first row per CTA
// (L1 persists within a launch), keeping regs at ~32 so occ=8 holds.

#define N_DIM   16384
#define THREADS 256
#define GRID_BLOCKS (148 * 8)

__global__ __launch_bounds__(THREADS, 8)
void matvec_rowsum_persistent(const float* __restrict__ S,
                              const float* __restrict__ w,
                              float* __restrict__ out)
{
    const int tid  = threadIdx.x;
    const int lane = tid & 31;
    const int wid  = tid >> 5;

    const float4* W4 = reinterpret_cast<const float4*>(w);

    __shared__ float warp_sums[THREADS / 32];

    for (int row = blockIdx.x; row < N_DIM; row += GRID_BLOCKS) {
        const float4* Srow = reinterpret_cast<const float4*>(S + (size_t)row * N_DIM);

        float acc = 0.0f;
        #pragma unroll
        for (int it = 0; it < 16; ++it) {
            const int idx = tid + it * THREADS;   // coalesced across warp
            float4 s  = __ldg(&Srow[idx]);
            float4 wv = __ldg(&W4[idx]);          // L1 hit after first row
            acc = fmaf(s.x, wv.x, acc);
            acc = fmaf(s.y, wv.y, acc);
            acc = fmaf(s.z, wv.z, acc);
            acc = fmaf(s.w, wv.w, acc);
        }

        // Warp reduction
        #pragma unroll
        for (int off = 16; off > 0; off >>= 1)
            acc += __shfl_xor_sync(0xFFFFFFFFu, acc, off);

        if (lane == 0) warp_sums[wid] = acc;
        __syncthreads();

        if (wid == 0) {
            float v = (lane < THREADS / 32) ? warp_sums[lane] : 0.0f;
            #pragma unroll
            for (int off = 4; off > 0; off >>= 1)
                v += __shfl_xor_sync(0xFFFFFFFFu, v, off);
            if (lane == 0) out[row] = v;
        }
        __syncthreads();   // protect warp_sums before next row reuses it
    }
}

extern "C" void kernel_launch(void* const* d_in, const int* in_sizes, int n_in,
                              void* d_out, int out_size)
{
    const float* S = (const float*)d_in[0];
    const float* w = (const float*)d_in[1];
    float* out = (float*)d_out;

    matvec_rowsum_persistent<<<GRID_BLOCKS, THREADS>>>(S, w, out);
}

// round 6
// speedup vs baseline: 2.1557x; 2.1557x over previous
#include <cuda_runtime.h>

// out[i] = sum_j S[i][j] * w[j],  N = 16384.
// R1 structure (one row per CTA, 16384 blocks, launch-ordered contiguous
// streaming) — proven 148.5us / 91.5% DRAM. Change vs R1: 128-thread CTAs at
// occupancy 16 instead of 256-thread at occ 8, so a retiring CTA (loads
// drained during its final reduction) idles 1/16 of the SM's load capacity
// instead of 1/8, and the launch tail is finer-grained.
// Loads issued in batches of 8 float4 (front-loaded) to keep MLP high while
// staying within the 32-reg budget (2048 thr/SM x 32 regs = full RF).

#define N_DIM   16384
#define THREADS 128

__global__ __launch_bounds__(THREADS, 16)
void matvec_rowsum_kernel(const float* __restrict__ S,
                          const float* __restrict__ w,
                          float* __restrict__ out)
{
    const int row = blockIdx.x;
    const int tid = threadIdx.x;
    const int lane = tid & 31;
    const int wid  = tid >> 5;

    const float4* Srow = reinterpret_cast<const float4*>(S + (size_t)row * N_DIM);
    const float4* W4   = reinterpret_cast<const float4*>(w);

    // 4096 float4 per row / 128 threads = 32 float4 per thread,
    // processed as 4 batches of 8 (8 S-loads issued back-to-back per batch).
    float acc = 0.0f;
    #pragma unroll
    for (int b = 0; b < 4; ++b) {
        float4 s[8];
        #pragma unroll
        for (int k = 0; k < 8; ++k)
            s[k] = __ldg(&Srow[tid + (b * 8 + k) * THREADS]);
        #pragma unroll
        for (int k = 0; k < 8; ++k) {
            float4 wv = __ldg(&W4[tid + (b * 8 + k) * THREADS]);
            acc = fmaf(s[k].x, wv.x, acc);
            acc = fmaf(s[k].y, wv.y, acc);
            acc = fmaf(s[k].z, wv.z, acc);
            acc = fmaf(s[k].w, wv.w, acc);
        }
    }

    // Warp reduction
    #pragma unroll
    for (int off = 16; off > 0; off >>= 1)
        acc += __shfl_xor_sync(0xFFFFFFFFu, acc, off);

    // Cross-warp reduction (4 warps)
    __shared__ float warp_sums[THREADS / 32];
    if (lane == 0) warp_sums[wid] = acc;
    __syncthreads();

    if (tid == 0) {
        float v = warp_sums[0] + warp_sums[1] + warp_sums[2] + warp_sums[3];
        out[row] = v;
    }
}

extern "C" void kernel_launch(void* const* d_in, const int* in_sizes, int n_in,
                              void* d_out, int out_size)
{
    const float* S = (const float*)d_in[0];
    const float* w = (const float*)d_in[1];
    float* out = (float*)d_out;

    matvec_rowsum_kernel<<<N_DIM, THREADS>>>(S, w, out);
}

// round 9
// speedup vs baseline: 2.1846x; 1.0134x over previous
#include <cuda_runtime.h>

// out[i] = sum_j S[i][j] * w[j],  N = 16384.
// R1 winner structure (one row per CTA, 256 threads, 16384 blocks, occ 8).
// Change: S loaded with __ldcs (evict-first streaming policy) — S has zero
// reuse and 1.07 GB of it otherwise churns L2, evicting the 64 KB w vector
// that is re-read by every CTA. w keeps the default (evict-normal) policy so
// it stays L2-resident for all 16384 row passes.

#define N_DIM   16384
#define THREADS 256

__global__ __launch_bounds__(THREADS, 8)
void matvec_rowsum_kernel(const float* __restrict__ S,
                          const float* __restrict__ w,
                          float* __restrict__ out)
{
    const int row = blockIdx.x;
    const int tid = threadIdx.x;
    const int lane = tid & 31;
    const int wid  = tid >> 5;

    const float4* Srow = reinterpret_cast<const float4*>(S + (size_t)row * N_DIM);
    const float4* W4   = reinterpret_cast<const float4*>(w);

    // 4096 float4 per row / 256 threads = 16 float4 per thread.
    float acc = 0.0f;
    #pragma unroll
    for (int it = 0; it < 16; ++it) {
        const int idx = tid + it * THREADS;    // coalesced across warp
        float4 s  = __ldcs(&Srow[idx]);        // streaming: evict-first
        float4 wv = __ldg(&W4[idx]);           // resident: default policy
        acc = fmaf(s.x, wv.x, acc);
        acc = fmaf(s.y, wv.y, acc);
        acc = fmaf(s.z, wv.z, acc);
        acc = fmaf(s.w, wv.w, acc);
    }

    // Warp reduction
    #pragma unroll
    for (int off = 16; off > 0; off >>= 1)
        acc += __shfl_xor_sync(0xFFFFFFFFu, acc, off);

    // Cross-warp reduction (8 warps)
    __shared__ float warp_sums[THREADS / 32];
    if (lane == 0) warp_sums[wid] = acc;
    __syncthreads();

    if (wid == 0) {
        float v = (lane < THREADS / 32) ? warp_sums[lane] : 0.0f;
        #pragma unroll
        for (int off = 4; off > 0; off >>= 1)
            v += __shfl_xor_sync(0xFFFFFFFFu, v, off);
        if (lane == 0) out[row] = v;
    }
}

extern "C" void kernel_launch(void* const* d_in, const int* in_sizes, int n_in,
                              void* d_out, int out_size)
{
    const float* S = (const float*)d_in[0];
    const float* w = (const float*)d_in[1];
    float* out = (float*)d_out;

    matvec_rowsum_kernel<<<N_DIM, THREADS>>>(S, w, out);
}